// round 13
// baseline (speedup 1.0000x reference)
#include <cuda_runtime.h>
#include <cuda_fp16.h>
#include <mma.h>

using namespace nvcuda;

// Problem constants (fixed shapes from reference setup_inputs)
constexpr int NN  = 100000;   // nodes
constexpr int EE  = 1600000;  // edges
constexpr int HID = 128;
constexpr int OUTC = 64;

constexpr int SCAN_B = 1024;
constexpr int NPART  = (NN + SCAN_B - 1) / SCAN_B;   // 98

// ---------------- scratch (static device globals; allocation-free) ----------
__device__ __half g_xh[NN * 128];   // x in fp16 (gemm1 A)
__device__ __half g_h1[NN * HID];   // x @ W_src1 (fp16)
__device__ __half g_a1h[NN * HID];  // layer1 output relu(agg+b) in fp16 (gemm2 A)
__device__ __half g_h2[NN * OUTC];  // layer2 gemm out (fp16)
__device__ __half g_W1h[128 * HID];
__device__ __half g_W2h[128 * OUTC];
__device__ float  g_asrc[NN];       // layer-1 attention scalars
__device__ float  g_adst[NN];
__device__ float  g_asrc2[NN];      // layer-2 attention scalars
__device__ float  g_adst2[NN];
__device__ float  g_wa1[2 * 128];   // [wa_src | wa_dst] layer 1
__device__ float  g_wa2[2 * 128];   // [wa_src | wa_dst] layer 2

__device__ int    g_cnt[NN];        // histogram (zero-init; self-cleaned by scan1)
__device__ int    g_off[NN + 1];    // CSR offsets by destination
__device__ int    g_part[NPART];    // scan partials
__device__ int    g_rank[EE];       // per-edge rank within its destination
__device__ int    g_csrc[EE];       // source node of each dst-sorted edge

// ---------------- packed f32x2 helpers --------------------------------------
__device__ __forceinline__ unsigned long long pack2(float lo, float hi) {
    unsigned long long r;
    asm("mov.b64 %0, {%1, %2};" : "=l"(r) : "f"(lo), "f"(hi));
    return r;
}
__device__ __forceinline__ void unpack2(unsigned long long v, float& lo, float& hi) {
    asm("mov.b64 {%0, %1}, %2;" : "=f"(lo), "=f"(hi) : "l"(v));
}
__device__ __forceinline__ void fma2(unsigned long long& acc,
                                     unsigned long long a, unsigned long long b) {
    asm("fma.rn.f32x2 %0, %1, %2, %0;" : "+l"(acc) : "l"(a), "l"(b));
}
__device__ __forceinline__ unsigned h2u(__half2 h) {
    return *(unsigned*)&h;
}

// ---------------- wa = W @ att (both src and dst), 128 outputs --------------
__global__ void k_wa(const float* __restrict__ Wsrc, const float* __restrict__ asrc,
                     const float* __restrict__ Wdst, const float* __restrict__ adst,
                     int cols, float* __restrict__ wa) {
    int k = threadIdx.x;  // 128 threads, one per input-feature row of W
    float s1 = 0.f, s2 = 0.f;
    for (int j = 0; j < cols; j++) {
        s1 += Wsrc[k * cols + j] * asrc[j];
        s2 += Wdst[k * cols + j] * adst[j];
    }
    wa[k]       = s1;
    wa[128 + k] = s2;
}

// ---------------- convert both W matrices to fp16 ---------------------------
__global__ __launch_bounds__(256) void k_cvtW(const float* __restrict__ W1,
                                              const float* __restrict__ W2) {
    for (int i = threadIdx.x + blockIdx.x * 256; i < 128 * HID; i += gridDim.x * 256)
        g_W1h[i] = __float2half_rn(W1[i]);
    for (int i = threadIdx.x + blockIdx.x * 256; i < 128 * OUTC; i += gridDim.x * 256)
        g_W2h[i] = __float2half_rn(W2[i]);
}

// ---------------- convert x to fp16 + layer-1 attention scalars -------------
__global__ __launch_bounds__(256) void k_cvtX(const float* __restrict__ X,
                                              const float* __restrict__ wa) {
    int warp = threadIdx.x >> 5, lane = threadIdx.x & 31;
    int n = blockIdx.x * 8 + warp;
    if (n >= NN) return;
    float4 v = ((const float4*)X)[n * 32 + lane];
    __half2 h0 = __floats2half2_rn(v.x, v.y);
    __half2 h1 = __floats2half2_rn(v.z, v.w);
    ((uint2*)g_xh)[n * 32 + lane] = make_uint2(h2u(h0), h2u(h1));   // 32 uint2/row!
    float4 ws = ((const float4*)wa)[lane];
    float4 wd = ((const float4*)(wa + 128))[lane];
    float s1 = v.x * ws.x + v.y * ws.y + v.z * ws.z + v.w * ws.w;
    float s2 = v.x * wd.x + v.y * wd.y + v.z * wd.z + v.w * wd.w;
#pragma unroll
    for (int o = 16; o > 0; o >>= 1) {
        s1 += __shfl_xor_sync(0xffffffffu, s1, o);
        s2 += __shfl_xor_sync(0xffffffffu, s2, o);
    }
    if (lane == 0) { g_asrc[n] = s1; g_adst[n] = s2; }
}

// ---------------- WMMA GEMM: Y[N,COLS](fp16) = Xh[N,128] @ Wh[128,COLS] -----
// CTA: 64 rows x COLS; 8 warps; warp = 16-row tile x COLS/2 cols.
template <int COLS>
__global__ __launch_bounds__(256) void k_gemm_wmma(const __half* __restrict__ Xh,
                                                   const __half* __restrict__ Wh,
                                                   __half* __restrict__ Y) {
    constexpr int NFRAG = (COLS / 2) / 16;           // 4 or 2
    extern __shared__ char sm[];
    __half* As = (__half*)sm;                        // 64 x 128, ld=128
    __half* Bs = (__half*)(sm + 64 * 128 * 2);       // 128 x COLS, ld=COLS
    float*  Cs = (float*)(sm + 64 * 128 * 2 + 128 * COLS * 2);  // 256 per warp

    const int row0 = blockIdx.x * 64;
    const int t = threadIdx.x;
    const int warp = t >> 5, lane = t & 31;

    // stage A (64 rows, clamped) and B
    for (int i = t; i < 64 * 16; i += 256) {         // 16 uint4 per row
        int r = i >> 4, c = i & 15;
        int rr = min(row0 + r, NN - 1);
        ((uint4*)As)[r * 16 + c] = ((const uint4*)Xh)[rr * 16 + c];
    }
    for (int i = t; i < 128 * COLS / 8; i += 256)
        ((uint4*)Bs)[i] = ((const uint4*)Wh)[i];
    __syncthreads();

    const int mrow  = (warp & 3) * 16;
    const int ncol0 = (warp >> 2) * (COLS / 2);

    wmma::fragment<wmma::accumulator, 16, 16, 16, float> acc[NFRAG];
#pragma unroll
    for (int f = 0; f < NFRAG; f++) wmma::fill_fragment(acc[f], 0.f);

#pragma unroll
    for (int k = 0; k < 128; k += 16) {
        wmma::fragment<wmma::matrix_a, 16, 16, 16, __half, wmma::row_major> a;
        wmma::load_matrix_sync(a, &As[mrow * 128 + k], 128);
#pragma unroll
        for (int f = 0; f < NFRAG; f++) {
            wmma::fragment<wmma::matrix_b, 16, 16, 16, __half, wmma::row_major> b;
            wmma::load_matrix_sync(b, &Bs[k * COLS + ncol0 + f * 16], COLS);
            wmma::mma_sync(acc[f], a, b, acc[f]);
        }
    }

    // store: stage f32 in smem, convert to fp16, write
    float* myC = Cs + warp * 256;
#pragma unroll
    for (int f = 0; f < NFRAG; f++) {
        wmma::store_matrix_sync(myC, acc[f], 16, wmma::mem_row_major);
        __syncwarp();
        int r  = lane >> 1;
        int ch = (lane & 1) * 8;
        int row = row0 + mrow + r;
        if (row < NN) {
            const float* cp = myC + r * 16 + ch;
            __half2 p0 = __floats2half2_rn(cp[0], cp[1]);
            __half2 p1 = __floats2half2_rn(cp[2], cp[3]);
            __half2 p2 = __floats2half2_rn(cp[4], cp[5]);
            __half2 p3 = __floats2half2_rn(cp[6], cp[7]);
            *(uint4*)&Y[row * COLS + ncol0 + f * 16 + ch] =
                make_uint4(h2u(p0), h2u(p1), h2u(p2), h2u(p3));
        }
        __syncwarp();
    }
}

// ======================= CSR build (by destination) =========================
__global__ void k_hist(const int* __restrict__ dst) {
    int i = blockIdx.x * blockDim.x + threadIdx.x;
    if (i < EE) g_rank[i] = atomicAdd(&g_cnt[dst[i]], 1);
}

__global__ __launch_bounds__(SCAN_B) void k_scan1() {
    __shared__ int sh[SCAN_B];
    int i = blockIdx.x * SCAN_B + threadIdx.x;
    int v = (i < NN) ? g_cnt[i] : 0;
    if (i < NN) g_cnt[i] = 0;          // restore invariant for next launch
    sh[threadIdx.x] = v;
    __syncthreads();
#pragma unroll
    for (int d = 1; d < SCAN_B; d <<= 1) {
        int t = (threadIdx.x >= d) ? sh[threadIdx.x - d] : 0;
        __syncthreads();
        sh[threadIdx.x] += t;
        __syncthreads();
    }
    if (i < NN) g_off[i] = sh[threadIdx.x] - v;
    if (threadIdx.x == SCAN_B - 1) g_part[blockIdx.x] = sh[SCAN_B - 1];
}

__global__ __launch_bounds__(128) void k_scan2() {
    __shared__ int sh[128];
    int t = threadIdx.x;
    int v = (t < NPART) ? g_part[t] : 0;
    sh[t] = v;
    __syncthreads();
#pragma unroll
    for (int d = 1; d < 128; d <<= 1) {
        int u = (t >= d) ? sh[t - d] : 0;
        __syncthreads();
        sh[t] += u;
        __syncthreads();
    }
    if (t < NPART) g_part[t] = sh[t] - v;
}

__global__ __launch_bounds__(SCAN_B) void k_scan3() {
    int i = blockIdx.x * SCAN_B + threadIdx.x;
    if (i < NN) g_off[i] += g_part[blockIdx.x];
    if (i == 0) g_off[NN] = EE;
}

__global__ void k_scatter(const int* __restrict__ src, const int* __restrict__ dst) {
    int i = blockIdx.x * blockDim.x + threadIdx.x;
    if (i >= EE) return;
    g_csrc[g_off[dst[i]] + g_rank[i]] = src[i];
}

// =================== fused per-node softmax + aggregation ===================
// One warp per node. FUSE (layer1): relu + fp16 output + layer-2 att scalars.
// !FUSE (layer2): fp32 output.
template <int C, bool FUSE>
__global__ __launch_bounds__(256) void k_agg(const __half* __restrict__ H,
                                             const float* __restrict__ bias,
                                             const float* __restrict__ aS,
                                             const float* __restrict__ aD,
                                             float* __restrict__ OutF,
                                             __half* __restrict__ OutH,
                                             const float* __restrict__ wa2) {
    __shared__ int2 stage[8][32];
    int warp = threadIdx.x >> 5;
    int lane = threadIdx.x & 31;
    int n = blockIdx.x * 8 + warp;
    if (n >= NN) return;

    int beg = g_off[n];
    int end = g_off[n + 1];
    float ad = aD[n];

    unsigned long long a01 = 0ull, a23 = 0ull;
    float denom = 0.f;

    for (int j0 = beg; j0 < end; j0 += 32) {
        int j = j0 + lane;
        int s = 0;
        float w = 0.f;
        if (j < end) {
            s = g_csrc[j];
            float e = aS[s] + ad;
            e = e > 0.f ? e : 0.2f * e;
            w = __expf(e);
        }
        denom += w;
        stage[warp][lane] = make_int2(s, __float_as_int(w));
        __syncwarp();

        int cnt = min(32, end - j0);
        if (cnt == 32) {
#pragma unroll
            for (int k = 0; k < 32; k++) {
                int2 sw = stage[warp][k];
                float wk = __int_as_float(sw.y);
                unsigned long long w2 = pack2(wk, wk);
                if (C == 128) {
                    uint2 raw = *(const uint2*)&H[sw.x * 128 + lane * 4];
                    float2 f0 = __half22float2(*(const __half2*)&raw.x);
                    float2 f1 = __half22float2(*(const __half2*)&raw.y);
                    fma2(a01, pack2(f0.x, f0.y), w2);
                    fma2(a23, pack2(f1.x, f1.y), w2);
                } else {
                    unsigned raw = *(const unsigned*)&H[sw.x * 64 + lane * 2];
                    float2 f0 = __half22float2(*(const __half2*)&raw);
                    fma2(a01, pack2(f0.x, f0.y), w2);
                }
            }
        } else {
#pragma unroll 16
            for (int k = 0; k < cnt; k++) {
                int2 sw = stage[warp][k];
                float wk = __int_as_float(sw.y);
                unsigned long long w2 = pack2(wk, wk);
                if (C == 128) {
                    uint2 raw = *(const uint2*)&H[sw.x * 128 + lane * 4];
                    float2 f0 = __half22float2(*(const __half2*)&raw.x);
                    float2 f1 = __half22float2(*(const __half2*)&raw.y);
                    fma2(a01, pack2(f0.x, f0.y), w2);
                    fma2(a23, pack2(f1.x, f1.y), w2);
                } else {
                    unsigned raw = *(const unsigned*)&H[sw.x * 64 + lane * 2];
                    float2 f0 = __half22float2(*(const __half2*)&raw);
                    fma2(a01, pack2(f0.x, f0.y), w2);
                }
            }
        }
        __syncwarp();
    }
#pragma unroll
    for (int o = 16; o > 0; o >>= 1)
        denom += __shfl_xor_sync(0xffffffffu, denom, o);
    float inv = (end > beg) ? __frcp_rn(denom) : 0.f;

    if (C == 128) {
        float a0, a1, a2, a3;
        unpack2(a01, a0, a1);
        unpack2(a23, a2, a3);
        float4 b4 = *(const float4*)&bias[lane * 4];
        float4 v;
        v.x = a0 * inv + b4.x;
        v.y = a1 * inv + b4.y;
        v.z = a2 * inv + b4.z;
        v.w = a3 * inv + b4.w;
        if (FUSE) {
            v.x = fmaxf(v.x, 0.f); v.y = fmaxf(v.y, 0.f);
            v.z = fmaxf(v.z, 0.f); v.w = fmaxf(v.w, 0.f);
            // fp16 output for gemm2
            __half2 p0 = __floats2half2_rn(v.x, v.y);
            __half2 p1 = __floats2half2_rn(v.z, v.w);
            *(uint2*)&OutH[n * 128 + lane * 4] = make_uint2(h2u(p0), h2u(p1));
            // layer-2 attention scalars (exact fp32)
            float4 ws = ((const float4*)wa2)[lane];
            float4 wd = ((const float4*)(wa2 + 128))[lane];
            float s1 = v.x * ws.x + v.y * ws.y + v.z * ws.z + v.w * ws.w;
            float s2 = v.x * wd.x + v.y * wd.y + v.z * wd.z + v.w * wd.w;
#pragma unroll
            for (int o = 16; o > 0; o >>= 1) {
                s1 += __shfl_xor_sync(0xffffffffu, s1, o);
                s2 += __shfl_xor_sync(0xffffffffu, s2, o);
            }
            if (lane == 0) { g_asrc2[n] = s1; g_adst2[n] = s2; }
        } else {
            *(float4*)&OutF[n * 128 + lane * 4] = v;
        }
    } else {
        float a0, a1;
        unpack2(a01, a0, a1);
        float2 b2 = *(const float2*)&bias[lane * 2];
        float2 v;
        v.x = a0 * inv + b2.x;
        v.y = a1 * inv + b2.y;
        *(float2*)&OutF[n * 64 + lane * 2] = v;
    }
}

// ---------------- launch ----------------------------------------------------
static cudaStream_t g_s2 = nullptr;
static cudaEvent_t  g_evF = nullptr, g_evJ = nullptr;

extern "C" void kernel_launch(void* const* d_in, const int* in_sizes, int n_in,
                              void* d_out, int out_size) {
    const float* x    = (const float*)d_in[0];
    const int*   ei   = (const int*)d_in[1];
    const float* Ws1  = (const float*)d_in[2];
    const float* Wd1  = (const float*)d_in[3];
    const float* as1  = (const float*)d_in[4];
    const float* ad1  = (const float*)d_in[5];
    const float* b1   = (const float*)d_in[6];
    const float* Ws2  = (const float*)d_in[7];
    const float* Wd2  = (const float*)d_in[8];
    const float* as2  = (const float*)d_in[9];
    const float* ad2  = (const float*)d_in[10];
    const float* b2   = (const float*)d_in[11];
    float* out = (float*)d_out;

    const int* src = ei;
    const int* dst = ei + EE;

    __half *p_xh, *p_h1, *p_a1h, *p_h2, *p_W1h, *p_W2h;
    float  *p_wa1, *p_wa2, *p_as, *p_ad, *p_as2, *p_ad2;
    cudaGetSymbolAddress((void**)&p_xh, g_xh);
    cudaGetSymbolAddress((void**)&p_h1, g_h1);
    cudaGetSymbolAddress((void**)&p_a1h, g_a1h);
    cudaGetSymbolAddress((void**)&p_h2, g_h2);
    cudaGetSymbolAddress((void**)&p_W1h, g_W1h);
    cudaGetSymbolAddress((void**)&p_W2h, g_W2h);
    cudaGetSymbolAddress((void**)&p_wa1, g_wa1);
    cudaGetSymbolAddress((void**)&p_wa2, g_wa2);
    cudaGetSymbolAddress((void**)&p_as, g_asrc);
    cudaGetSymbolAddress((void**)&p_ad, g_adst);
    cudaGetSymbolAddress((void**)&p_as2, g_asrc2);
    cudaGetSymbolAddress((void**)&p_ad2, g_adst2);

    constexpr int SM1 = 64 * 128 * 2 + 128 * HID * 2 + 8 * 256 * 4;   // 57344
    constexpr int SM2 = 64 * 128 * 2 + 128 * OUTC * 2 + 8 * 256 * 4;  // 40960

    if (!g_s2) {
        cudaStreamCreateWithFlags(&g_s2, cudaStreamNonBlocking);
        cudaEventCreateWithFlags(&g_evF, cudaEventDisableTiming);
        cudaEventCreateWithFlags(&g_evJ, cudaEventDisableTiming);
        cudaFuncSetAttribute(k_gemm_wmma<HID>,
                             cudaFuncAttributeMaxDynamicSharedMemorySize, SM1);
        cudaFuncSetAttribute(k_gemm_wmma<OUTC>,
                             cudaFuncAttributeMaxDynamicSharedMemorySize, SM2);
    }

    const int TB = 256;
    const int edge_blocks = (EE + TB - 1) / TB;
    const int agg_blocks  = (NN + 7) / 8;
    const int gemm_blocks = (NN + 63) / 64;   // 1563

    cudaEventRecord(g_evF, 0);
    cudaStreamWaitEvent(g_s2, g_evF, 0);

    // ---------- main: layer-1 dense path ----------
    k_wa<<<1, 128>>>(Ws1, as1, Wd1, ad1, HID, p_wa1);                  // 1
    k_cvtW<<<48, 256>>>(Ws1, Ws2);                                     // 2
    k_cvtX<<<agg_blocks, 256>>>(x, p_wa1);                             // 3
    k_gemm_wmma<HID><<<gemm_blocks, 256, SM1>>>(p_xh, p_W1h, p_h1);    // 4 (profiled)

    // ---------- side stream: CSR build (overlaps dense path) ----------
    k_hist<<<edge_blocks, TB, 0, g_s2>>>(dst);
    k_scan1<<<NPART, SCAN_B, 0, g_s2>>>();
    k_scan2<<<1, 128, 0, g_s2>>>();
    k_scan3<<<NPART, SCAN_B, 0, g_s2>>>();
    k_scatter<<<edge_blocks, TB, 0, g_s2>>>(src, dst);
    cudaEventRecord(g_evJ, g_s2);

    k_wa<<<1, 128>>>(Ws2, as2, Wd2, ad2, OUTC, p_wa2);

    // ---------- layer 1 aggregation (join; fused: fp16 out + att2) ----------
    cudaStreamWaitEvent(0, g_evJ, 0);
    k_agg<HID, true><<<agg_blocks, TB>>>(p_h1, b1, p_as, p_ad,
                                         nullptr, p_a1h, p_wa2);

    // ---------- layer 2 ----------
    k_gemm_wmma<OUTC><<<gemm_blocks, 256, SM2>>>(p_a1h, p_W2h, p_h2);
    k_agg<OUTC, false><<<agg_blocks, TB>>>(p_h2, b2, p_as2, p_ad2,
                                           out, nullptr, nullptr);
}

// round 14
// speedup vs baseline: 1.9265x; 1.9265x over previous
#include <cuda_runtime.h>
#include <cuda_fp16.h>
#include <mma.h>

using namespace nvcuda;

// Problem constants (fixed shapes from reference setup_inputs)
constexpr int NN  = 100000;   // nodes
constexpr int EE  = 1600000;  // edges
constexpr int HID = 128;
constexpr int OUTC = 64;

constexpr int SCAN_B = 1024;
constexpr int NPART  = (NN + SCAN_B - 1) / SCAN_B;   // 98

// ---------------- scratch (static device globals; allocation-free) ----------
__device__ __half g_xh[NN * 128];   // x in fp16 (gemm1 A)
__device__ __half g_h1[NN * HID];   // x @ W_src1 (fp16)
__device__ __half g_a1h[NN * HID];  // layer1 output relu(agg+b) in fp16 (gemm2 A)
__device__ __half g_h2[NN * OUTC];  // layer2 gemm out (fp16)
__device__ __half g_W1h[128 * HID];
__device__ __half g_W2h[128 * OUTC];
__device__ float  g_asrc[NN];       // layer-1 attention scalars
__device__ float  g_adst[NN];
__device__ float  g_asrc2[NN];      // layer-2 attention scalars
__device__ float  g_adst2[NN];
__device__ float  g_wa1[2 * 128];   // [wa_src | wa_dst] layer 1
__device__ float  g_wa2[2 * 128];   // [wa_src | wa_dst] layer 2

__device__ int    g_cnt[NN];        // histogram (zero-init; self-cleaned by scan1)
__device__ int    g_off[NN + 1];    // CSR offsets by destination
__device__ int    g_part[NPART];    // scan partials
__device__ int    g_rank[EE];       // per-edge rank within its destination
__device__ int    g_csrc[EE];       // source node of each dst-sorted edge

// ---------------- packed f32x2 helpers --------------------------------------
__device__ __forceinline__ unsigned long long pack2(float lo, float hi) {
    unsigned long long r;
    asm("mov.b64 %0, {%1, %2};" : "=l"(r) : "f"(lo), "f"(hi));
    return r;
}
__device__ __forceinline__ void unpack2(unsigned long long v, float& lo, float& hi) {
    asm("mov.b64 {%0, %1}, %2;" : "=f"(lo), "=f"(hi) : "l"(v));
}
__device__ __forceinline__ void fma2(unsigned long long& acc,
                                     unsigned long long a, unsigned long long b) {
    asm("fma.rn.f32x2 %0, %1, %2, %0;" : "+l"(acc) : "l"(a), "l"(b));
}
__device__ __forceinline__ unsigned h2u(__half2 h) {
    return *(unsigned*)&h;
}

// ---------------- wa = W @ att (both src and dst), 128 outputs --------------
__global__ void k_wa(const float* __restrict__ Wsrc, const float* __restrict__ asrc,
                     const float* __restrict__ Wdst, const float* __restrict__ adst,
                     int cols, float* __restrict__ wa) {
    int k = threadIdx.x;  // 128 threads, one per input-feature row of W
    float s1 = 0.f, s2 = 0.f;
    for (int j = 0; j < cols; j++) {
        s1 += Wsrc[k * cols + j] * asrc[j];
        s2 += Wdst[k * cols + j] * adst[j];
    }
    wa[k]       = s1;
    wa[128 + k] = s2;
}

// ---------------- convert both W matrices to fp16 ---------------------------
__global__ __launch_bounds__(256) void k_cvtW(const float* __restrict__ W1,
                                              const float* __restrict__ W2) {
    for (int i = threadIdx.x + blockIdx.x * 256; i < 128 * HID; i += gridDim.x * 256)
        g_W1h[i] = __float2half_rn(W1[i]);
    for (int i = threadIdx.x + blockIdx.x * 256; i < 128 * OUTC; i += gridDim.x * 256)
        g_W2h[i] = __float2half_rn(W2[i]);
}

// ---------------- convert x to fp16 + layer-1 attention scalars -------------
__global__ __launch_bounds__(256) void k_cvtX(const float* __restrict__ X,
                                              const float* __restrict__ wa) {
    int warp = threadIdx.x >> 5, lane = threadIdx.x & 31;
    int n = blockIdx.x * 8 + warp;
    if (n >= NN) return;
    float4 v = ((const float4*)X)[n * 32 + lane];
    __half2 h0 = __floats2half2_rn(v.x, v.y);
    __half2 h1 = __floats2half2_rn(v.z, v.w);
    ((uint2*)g_xh)[n * 32 + lane] = make_uint2(h2u(h0), h2u(h1));
    float4 ws = ((const float4*)wa)[lane];
    float4 wd = ((const float4*)(wa + 128))[lane];
    float s1 = v.x * ws.x + v.y * ws.y + v.z * ws.z + v.w * ws.w;
    float s2 = v.x * wd.x + v.y * wd.y + v.z * wd.z + v.w * wd.w;
#pragma unroll
    for (int o = 16; o > 0; o >>= 1) {
        s1 += __shfl_xor_sync(0xffffffffu, s1, o);
        s2 += __shfl_xor_sync(0xffffffffu, s2, o);
    }
    if (lane == 0) { g_asrc[n] = s1; g_adst[n] = s2; }
}

// ---------------- WMMA GEMM: Y[N,COLS](fp16) = Xh[N,128] @ Wh[128,COLS] -----
// CTA: 64 rows x COLS; 8 warps; warp = 16-row tile x COLS/2 cols.
// Smem tiles padded by 8 halves (16B) per row -> conflict-free LDSM.
template <int COLS>
__global__ __launch_bounds__(256) void k_gemm_wmma(const __half* __restrict__ Xh,
                                                   const __half* __restrict__ Wh,
                                                   __half* __restrict__ Y) {
    constexpr int NFRAG = (COLS / 2) / 16;           // 4 or 2
    constexpr int ALD = 136;                         // A smem ld (halves)
    constexpr int BLD = COLS + 8;                    // B smem ld (halves)
    constexpr int AU4 = ALD / 8;                     // 17 uint4 per A row
    constexpr int BU4 = BLD / 8;                     // 17 or 9 uint4 per B row
    extern __shared__ char sm[];
    __half* As = (__half*)sm;                        // 64 x ALD
    __half* Bs = (__half*)(sm + 64 * ALD * 2);       // 128 x BLD
    float*  Cs = (float*)(sm + 64 * ALD * 2 + 128 * BLD * 2);  // 256 per warp

    const int row0 = blockIdx.x * 64;
    const int t = threadIdx.x;
    const int warp = t >> 5, lane = t & 31;

    // stage A (64 rows, clamped) and B, padded strides
    for (int i = t; i < 64 * 16; i += 256) {         // 16 data uint4 per row
        int r = i >> 4, c = i & 15;
        int rr = min(row0 + r, NN - 1);
        ((uint4*)As)[r * AU4 + c] = ((const uint4*)Xh)[rr * 16 + c];
    }
    for (int i = t; i < 128 * COLS / 8; i += 256) {
        int r = i / (COLS / 8), c = i % (COLS / 8);
        ((uint4*)Bs)[r * BU4 + c] = ((const uint4*)Wh)[i];
    }
    __syncthreads();

    const int mrow  = (warp & 3) * 16;
    const int ncol0 = (warp >> 2) * (COLS / 2);

    wmma::fragment<wmma::accumulator, 16, 16, 16, float> acc[NFRAG];
#pragma unroll
    for (int f = 0; f < NFRAG; f++) wmma::fill_fragment(acc[f], 0.f);

#pragma unroll
    for (int k = 0; k < 128; k += 16) {
        wmma::fragment<wmma::matrix_a, 16, 16, 16, __half, wmma::row_major> a;
        wmma::load_matrix_sync(a, &As[mrow * ALD + k], ALD);
#pragma unroll
        for (int f = 0; f < NFRAG; f++) {
            wmma::fragment<wmma::matrix_b, 16, 16, 16, __half, wmma::row_major> b;
            wmma::load_matrix_sync(b, &Bs[k * BLD + ncol0 + f * 16], BLD);
            wmma::mma_sync(acc[f], a, b, acc[f]);
        }
    }

    // store: stage f32 in smem, convert to fp16, write
    float* myC = Cs + warp * 256;
#pragma unroll
    for (int f = 0; f < NFRAG; f++) {
        wmma::store_matrix_sync(myC, acc[f], 16, wmma::mem_row_major);
        __syncwarp();
        int r  = lane >> 1;
        int ch = (lane & 1) * 8;
        int row = row0 + mrow + r;
        if (row < NN) {
            const float* cp = myC + r * 16 + ch;
            __half2 p0 = __floats2half2_rn(cp[0], cp[1]);
            __half2 p1 = __floats2half2_rn(cp[2], cp[3]);
            __half2 p2 = __floats2half2_rn(cp[4], cp[5]);
            __half2 p3 = __floats2half2_rn(cp[6], cp[7]);
            *(uint4*)&Y[row * COLS + ncol0 + f * 16 + ch] =
                make_uint4(h2u(p0), h2u(p1), h2u(p2), h2u(p3));
        }
        __syncwarp();
    }
}

// ======================= CSR build (by destination) =========================
__global__ void k_hist(const int* __restrict__ dst) {
    int i = blockIdx.x * blockDim.x + threadIdx.x;
    if (i < EE) g_rank[i] = atomicAdd(&g_cnt[dst[i]], 1);
}

__global__ __launch_bounds__(SCAN_B) void k_scan1() {
    __shared__ int sh[SCAN_B];
    int i = blockIdx.x * SCAN_B + threadIdx.x;
    int v = (i < NN) ? g_cnt[i] : 0;
    if (i < NN) g_cnt[i] = 0;          // restore invariant for next launch
    sh[threadIdx.x] = v;
    __syncthreads();
#pragma unroll
    for (int d = 1; d < SCAN_B; d <<= 1) {
        int t = (threadIdx.x >= d) ? sh[threadIdx.x - d] : 0;
        __syncthreads();
        sh[threadIdx.x] += t;
        __syncthreads();
    }
    if (i < NN) g_off[i] = sh[threadIdx.x] - v;
    if (threadIdx.x == SCAN_B - 1) g_part[blockIdx.x] = sh[SCAN_B - 1];
}

__global__ __launch_bounds__(128) void k_scan2() {
    __shared__ int sh[128];
    int t = threadIdx.x;
    int v = (t < NPART) ? g_part[t] : 0;
    sh[t] = v;
    __syncthreads();
#pragma unroll
    for (int d = 1; d < 128; d <<= 1) {
        int u = (t >= d) ? sh[t - d] : 0;
        __syncthreads();
        sh[t] += u;
        __syncthreads();
    }
    if (t < NPART) g_part[t] = sh[t] - v;
}

__global__ __launch_bounds__(SCAN_B) void k_scan3() {
    int i = blockIdx.x * SCAN_B + threadIdx.x;
    if (i < NN) g_off[i] += g_part[blockIdx.x];
    if (i == 0) g_off[NN] = EE;
}

__global__ void k_scatter(const int* __restrict__ src, const int* __restrict__ dst) {
    int i = blockIdx.x * blockDim.x + threadIdx.x;
    if (i >= EE) return;
    g_csrc[g_off[dst[i]] + g_rank[i]] = src[i];
}

// =================== fused per-node softmax + aggregation ===================
// One warp per node. FUSE (layer1): relu + fp16 output + layer-2 att scalars.
// !FUSE (layer2): fp32 output.
template <int C, bool FUSE>
__global__ __launch_bounds__(256) void k_agg(const __half* __restrict__ H,
                                             const float* __restrict__ bias,
                                             const float* __restrict__ aS,
                                             const float* __restrict__ aD,
                                             float* __restrict__ OutF,
                                             __half* __restrict__ OutH,
                                             const float* __restrict__ wa2) {
    __shared__ int2 stage[8][32];
    int warp = threadIdx.x >> 5;
    int lane = threadIdx.x & 31;
    int n = blockIdx.x * 8 + warp;
    if (n >= NN) return;

    int beg = g_off[n];
    int end = g_off[n + 1];
    float ad = aD[n];

    unsigned long long a01 = 0ull, a23 = 0ull;
    float denom = 0.f;

    for (int j0 = beg; j0 < end; j0 += 32) {
        int j = j0 + lane;
        int s = 0;
        float w = 0.f;
        if (j < end) {
            s = g_csrc[j];
            float e = aS[s] + ad;
            e = e > 0.f ? e : 0.2f * e;
            w = __expf(e);
        }
        denom += w;
        stage[warp][lane] = make_int2(s, __float_as_int(w));
        __syncwarp();

        int cnt = min(32, end - j0);
        if (cnt == 32) {
#pragma unroll
            for (int k = 0; k < 32; k++) {
                int2 sw = stage[warp][k];
                float wk = __int_as_float(sw.y);
                unsigned long long w2 = pack2(wk, wk);
                if (C == 128) {
                    uint2 raw = *(const uint2*)&H[sw.x * 128 + lane * 4];
                    float2 f0 = __half22float2(*(const __half2*)&raw.x);
                    float2 f1 = __half22float2(*(const __half2*)&raw.y);
                    fma2(a01, pack2(f0.x, f0.y), w2);
                    fma2(a23, pack2(f1.x, f1.y), w2);
                } else {
                    unsigned raw = *(const unsigned*)&H[sw.x * 64 + lane * 2];
                    float2 f0 = __half22float2(*(const __half2*)&raw);
                    fma2(a01, pack2(f0.x, f0.y), w2);
                }
            }
        } else {
#pragma unroll 16
            for (int k = 0; k < cnt; k++) {
                int2 sw = stage[warp][k];
                float wk = __int_as_float(sw.y);
                unsigned long long w2 = pack2(wk, wk);
                if (C == 128) {
                    uint2 raw = *(const uint2*)&H[sw.x * 128 + lane * 4];
                    float2 f0 = __half22float2(*(const __half2*)&raw.x);
                    float2 f1 = __half22float2(*(const __half2*)&raw.y);
                    fma2(a01, pack2(f0.x, f0.y), w2);
                    fma2(a23, pack2(f1.x, f1.y), w2);
                } else {
                    unsigned raw = *(const unsigned*)&H[sw.x * 64 + lane * 2];
                    float2 f0 = __half22float2(*(const __half2*)&raw);
                    fma2(a01, pack2(f0.x, f0.y), w2);
                }
            }
        }
        __syncwarp();
    }
#pragma unroll
    for (int o = 16; o > 0; o >>= 1)
        denom += __shfl_xor_sync(0xffffffffu, denom, o);
    float inv = (end > beg) ? __frcp_rn(denom) : 0.f;

    if (C == 128) {
        float a0, a1, a2, a3;
        unpack2(a01, a0, a1);
        unpack2(a23, a2, a3);
        float4 b4 = *(const float4*)&bias[lane * 4];
        float4 v;
        v.x = a0 * inv + b4.x;
        v.y = a1 * inv + b4.y;
        v.z = a2 * inv + b4.z;
        v.w = a3 * inv + b4.w;
        if (FUSE) {
            v.x = fmaxf(v.x, 0.f); v.y = fmaxf(v.y, 0.f);
            v.z = fmaxf(v.z, 0.f); v.w = fmaxf(v.w, 0.f);
            __half2 p0 = __floats2half2_rn(v.x, v.y);
            __half2 p1 = __floats2half2_rn(v.z, v.w);
            *(uint2*)&OutH[n * 128 + lane * 4] = make_uint2(h2u(p0), h2u(p1));
            float4 ws = ((const float4*)wa2)[lane];
            float4 wd = ((const float4*)(wa2 + 128))[lane];
            float s1 = v.x * ws.x + v.y * ws.y + v.z * ws.z + v.w * ws.w;
            float s2 = v.x * wd.x + v.y * wd.y + v.z * wd.z + v.w * wd.w;
#pragma unroll
            for (int o = 16; o > 0; o >>= 1) {
                s1 += __shfl_xor_sync(0xffffffffu, s1, o);
                s2 += __shfl_xor_sync(0xffffffffu, s2, o);
            }
            if (lane == 0) { g_asrc2[n] = s1; g_adst2[n] = s2; }
        } else {
            *(float4*)&OutF[n * 128 + lane * 4] = v;
        }
    } else {
        float a0, a1;
        unpack2(a01, a0, a1);
        float2 b2 = *(const float2*)&bias[lane * 2];
        float2 v;
        v.x = a0 * inv + b2.x;
        v.y = a1 * inv + b2.y;
        *(float2*)&OutF[n * 64 + lane * 2] = v;
    }
}

// ---------------- launch ----------------------------------------------------
static cudaStream_t g_s2 = nullptr;
static cudaEvent_t  g_evF = nullptr, g_evJ = nullptr;

extern "C" void kernel_launch(void* const* d_in, const int* in_sizes, int n_in,
                              void* d_out, int out_size) {
    const float* x    = (const float*)d_in[0];
    const int*   ei   = (const int*)d_in[1];
    const float* Ws1  = (const float*)d_in[2];
    const float* Wd1  = (const float*)d_in[3];
    const float* as1  = (const float*)d_in[4];
    const float* ad1  = (const float*)d_in[5];
    const float* b1   = (const float*)d_in[6];
    const float* Ws2  = (const float*)d_in[7];
    const float* Wd2  = (const float*)d_in[8];
    const float* as2  = (const float*)d_in[9];
    const float* ad2  = (const float*)d_in[10];
    const float* b2   = (const float*)d_in[11];
    float* out = (float*)d_out;

    const int* src = ei;
    const int* dst = ei + EE;

    __half *p_xh, *p_h1, *p_a1h, *p_h2, *p_W1h, *p_W2h;
    float  *p_wa1, *p_wa2, *p_as, *p_ad, *p_as2, *p_ad2;
    cudaGetSymbolAddress((void**)&p_xh, g_xh);
    cudaGetSymbolAddress((void**)&p_h1, g_h1);
    cudaGetSymbolAddress((void**)&p_a1h, g_a1h);
    cudaGetSymbolAddress((void**)&p_h2, g_h2);
    cudaGetSymbolAddress((void**)&p_W1h, g_W1h);
    cudaGetSymbolAddress((void**)&p_W2h, g_W2h);
    cudaGetSymbolAddress((void**)&p_wa1, g_wa1);
    cudaGetSymbolAddress((void**)&p_wa2, g_wa2);
    cudaGetSymbolAddress((void**)&p_as, g_asrc);
    cudaGetSymbolAddress((void**)&p_ad, g_adst);
    cudaGetSymbolAddress((void**)&p_as2, g_asrc2);
    cudaGetSymbolAddress((void**)&p_ad2, g_adst2);

    constexpr int SM1 = 64 * 136 * 2 + 128 * (HID + 8) * 2 + 8 * 256 * 4;   // 60416
    constexpr int SM2 = 64 * 136 * 2 + 128 * (OUTC + 8) * 2 + 8 * 256 * 4;  // 44032

    if (!g_s2) {
        cudaStreamCreateWithFlags(&g_s2, cudaStreamNonBlocking);
        cudaEventCreateWithFlags(&g_evF, cudaEventDisableTiming);
        cudaEventCreateWithFlags(&g_evJ, cudaEventDisableTiming);
        cudaFuncSetAttribute(k_gemm_wmma<HID>,
                             cudaFuncAttributeMaxDynamicSharedMemorySize, SM1);
        cudaFuncSetAttribute(k_gemm_wmma<OUTC>,
                             cudaFuncAttributeMaxDynamicSharedMemorySize, SM2);
    }

    const int TB = 256;
    const int edge_blocks = (EE + TB - 1) / TB;
    const int agg_blocks  = (NN + 7) / 8;
    const int gemm_blocks = (NN + 63) / 64;   // 1563

    cudaEventRecord(g_evF, 0);
    cudaStreamWaitEvent(g_s2, g_evF, 0);

    // ---------- main: layer-1 dense path ----------
    k_wa<<<1, 128>>>(Ws1, as1, Wd1, ad1, HID, p_wa1);                  // 1
    k_cvtW<<<48, 256>>>(Ws1, Ws2);                                     // 2
    k_cvtX<<<agg_blocks, 256>>>(x, p_wa1);                             // 3
    k_gemm_wmma<HID><<<gemm_blocks, 256, SM1>>>(p_xh, p_W1h, p_h1);    // 4 (profiled)

    // ---------- side stream: CSR build (overlaps dense path) ----------
    k_hist<<<edge_blocks, TB, 0, g_s2>>>(dst);
    k_scan1<<<NPART, SCAN_B, 0, g_s2>>>();
    k_scan2<<<1, 128, 0, g_s2>>>();
    k_scan3<<<NPART, SCAN_B, 0, g_s2>>>();
    k_scatter<<<edge_blocks, TB, 0, g_s2>>>(src, dst);
    cudaEventRecord(g_evJ, g_s2);

    k_wa<<<1, 128>>>(Ws2, as2, Wd2, ad2, OUTC, p_wa2);

    // ---------- layer 1 aggregation (join; fused: fp16 out + att2) ----------
    cudaStreamWaitEvent(0, g_evJ, 0);
    k_agg<HID, true><<<agg_blocks, TB>>>(p_h1, b1, p_as, p_ad,
                                         nullptr, p_a1h, p_wa2);

    // ---------- layer 2 ----------
    k_gemm_wmma<OUTC><<<gemm_blocks, 256, SM2>>>(p_a1h, p_W2h, p_h2);
    k_agg<OUTC, false><<<agg_blocks, TB>>>(p_h2, b2, p_as2, p_ad2,
                                           out, nullptr, nullptr);
}

// round 15
// speedup vs baseline: 2.0242x; 1.0507x over previous
#include <cuda_runtime.h>
#include <cuda_fp16.h>
#include <mma.h>

using namespace nvcuda;

// Problem constants (fixed shapes from reference setup_inputs)
constexpr int NN  = 100000;   // nodes
constexpr int EE  = 1600000;  // edges
constexpr int HID = 128;
constexpr int OUTC = 64;

constexpr int SCAN_B = 1024;
constexpr int NPART  = (NN + SCAN_B - 1) / SCAN_B;   // 98

// ---------------- scratch (static device globals; allocation-free) ----------
__device__ __half g_xh[NN * 128];   // x in fp16 (gemm1 A)
__device__ __half g_h1[NN * HID];   // x @ W_src1 (fp16)
__device__ __half g_a1h[NN * HID];  // layer1 output relu(agg+b) in fp16 (gemm2 A)
__device__ __half g_h2[NN * OUTC];  // layer2 gemm out (fp16)
__device__ __half g_W1h[128 * HID];
__device__ __half g_W2h[128 * OUTC];
__device__ float  g_asrc[NN];       // layer-1 attention scalars
__device__ float  g_adst[NN];
__device__ float  g_asrc2[NN];      // layer-2 attention scalars
__device__ float  g_adst2[NN];
__device__ float  g_wa1[2 * 128];   // [wa_src | wa_dst] layer 1
__device__ float  g_wa2[2 * 128];   // [wa_src | wa_dst] layer 2

__device__ int    g_cnt[NN];        // histogram (zero-init; self-cleaned by scan1)
__device__ int    g_off[NN + 1];    // CSR offsets by destination
__device__ int    g_part[NPART];    // scan partials
__device__ int    g_rank[EE];       // per-edge rank within its destination
__device__ int    g_csrc[EE];       // source node of each dst-sorted edge

// ---------------- packed f32x2 helpers --------------------------------------
__device__ __forceinline__ unsigned long long pack2(float lo, float hi) {
    unsigned long long r;
    asm("mov.b64 %0, {%1, %2};" : "=l"(r) : "f"(lo), "f"(hi));
    return r;
}
__device__ __forceinline__ void unpack2(unsigned long long v, float& lo, float& hi) {
    asm("mov.b64 {%0, %1}, %2;" : "=f"(lo), "=f"(hi) : "l"(v));
}
__device__ __forceinline__ void fma2(unsigned long long& acc,
                                     unsigned long long a, unsigned long long b) {
    asm("fma.rn.f32x2 %0, %1, %2, %0;" : "+l"(acc) : "l"(a), "l"(b));
}
__device__ __forceinline__ void add2(unsigned long long& acc, unsigned long long b) {
    asm("add.rn.f32x2 %0, %0, %1;" : "+l"(acc) : "l"(b));
}
__device__ __forceinline__ unsigned h2u(__half2 h) {
    return *(unsigned*)&h;
}

// ---------------- wa = W @ att (both src and dst), 128 outputs --------------
__global__ void k_wa(const float* __restrict__ Wsrc, const float* __restrict__ asrc,
                     const float* __restrict__ Wdst, const float* __restrict__ adst,
                     int cols, float* __restrict__ wa) {
    int k = threadIdx.x;  // 128 threads, one per input-feature row of W
    float s1 = 0.f, s2 = 0.f;
    for (int j = 0; j < cols; j++) {
        s1 += Wsrc[k * cols + j] * asrc[j];
        s2 += Wdst[k * cols + j] * adst[j];
    }
    wa[k]       = s1;
    wa[128 + k] = s2;
}

// ---------------- convert both W matrices to fp16 ---------------------------
__global__ __launch_bounds__(256) void k_cvtW(const float* __restrict__ W1,
                                              const float* __restrict__ W2) {
    for (int i = threadIdx.x + blockIdx.x * 256; i < 128 * HID; i += gridDim.x * 256)
        g_W1h[i] = __float2half_rn(W1[i]);
    for (int i = threadIdx.x + blockIdx.x * 256; i < 128 * OUTC; i += gridDim.x * 256)
        g_W2h[i] = __float2half_rn(W2[i]);
}

// ---------------- convert x to fp16 + layer-1 attention scalars -------------
__global__ __launch_bounds__(256) void k_cvtX(const float* __restrict__ X,
                                              const float* __restrict__ wa) {
    int warp = threadIdx.x >> 5, lane = threadIdx.x & 31;
    int n = blockIdx.x * 8 + warp;
    if (n >= NN) return;
    float4 v = ((const float4*)X)[n * 32 + lane];
    __half2 h0 = __floats2half2_rn(v.x, v.y);
    __half2 h1 = __floats2half2_rn(v.z, v.w);
    ((uint2*)g_xh)[n * 32 + lane] = make_uint2(h2u(h0), h2u(h1));
    float4 ws = ((const float4*)wa)[lane];
    float4 wd = ((const float4*)(wa + 128))[lane];
    float s1 = v.x * ws.x + v.y * ws.y + v.z * ws.z + v.w * ws.w;
    float s2 = v.x * wd.x + v.y * wd.y + v.z * wd.z + v.w * wd.w;
#pragma unroll
    for (int o = 16; o > 0; o >>= 1) {
        s1 += __shfl_xor_sync(0xffffffffu, s1, o);
        s2 += __shfl_xor_sync(0xffffffffu, s2, o);
    }
    if (lane == 0) { g_asrc[n] = s1; g_adst[n] = s2; }
}

// ---------------- WMMA GEMM: Y[N,COLS](fp16) = Xh[N,128] @ Wh[128,COLS] -----
// CTA: 64 rows x COLS; 8 warps; warp = 16-row tile x COLS/2 cols.
// Smem tiles padded by 8 halves (16B) per row -> conflict-free LDSM.
template <int COLS>
__global__ __launch_bounds__(256) void k_gemm_wmma(const __half* __restrict__ Xh,
                                                   const __half* __restrict__ Wh,
                                                   __half* __restrict__ Y) {
    constexpr int NFRAG = (COLS / 2) / 16;           // 4 or 2
    constexpr int ALD = 136;                         // A smem ld (halves)
    constexpr int BLD = COLS + 8;                    // B smem ld (halves)
    constexpr int AU4 = ALD / 8;                     // 17 uint4 per A row
    constexpr int BU4 = BLD / 8;                     // 17 or 9 uint4 per B row
    extern __shared__ char sm[];
    __half* As = (__half*)sm;                        // 64 x ALD
    __half* Bs = (__half*)(sm + 64 * ALD * 2);       // 128 x BLD
    float*  Cs = (float*)(sm + 64 * ALD * 2 + 128 * BLD * 2);  // 256 per warp

    const int row0 = blockIdx.x * 64;
    const int t = threadIdx.x;
    const int warp = t >> 5, lane = t & 31;

    // stage A (64 rows, clamped) and B, padded strides
    for (int i = t; i < 64 * 16; i += 256) {         // 16 data uint4 per row
        int r = i >> 4, c = i & 15;
        int rr = min(row0 + r, NN - 1);
        ((uint4*)As)[r * AU4 + c] = ((const uint4*)Xh)[rr * 16 + c];
    }
    for (int i = t; i < 128 * COLS / 8; i += 256) {
        int r = i / (COLS / 8), c = i % (COLS / 8);
        ((uint4*)Bs)[r * BU4 + c] = ((const uint4*)Wh)[i];
    }
    __syncthreads();

    const int mrow  = (warp & 3) * 16;
    const int ncol0 = (warp >> 2) * (COLS / 2);

    wmma::fragment<wmma::accumulator, 16, 16, 16, float> acc[NFRAG];
#pragma unroll
    for (int f = 0; f < NFRAG; f++) wmma::fill_fragment(acc[f], 0.f);

#pragma unroll
    for (int k = 0; k < 128; k += 16) {
        wmma::fragment<wmma::matrix_a, 16, 16, 16, __half, wmma::row_major> a;
        wmma::load_matrix_sync(a, &As[mrow * ALD + k], ALD);
#pragma unroll
        for (int f = 0; f < NFRAG; f++) {
            wmma::fragment<wmma::matrix_b, 16, 16, 16, __half, wmma::row_major> b;
            wmma::load_matrix_sync(b, &Bs[k * BLD + ncol0 + f * 16], BLD);
            wmma::mma_sync(acc[f], a, b, acc[f]);
        }
    }

    // store: stage f32 in smem, convert to fp16, write
    float* myC = Cs + warp * 256;
#pragma unroll
    for (int f = 0; f < NFRAG; f++) {
        wmma::store_matrix_sync(myC, acc[f], 16, wmma::mem_row_major);
        __syncwarp();
        int r  = lane >> 1;
        int ch = (lane & 1) * 8;
        int row = row0 + mrow + r;
        if (row < NN) {
            const float* cp = myC + r * 16 + ch;
            __half2 p0 = __floats2half2_rn(cp[0], cp[1]);
            __half2 p1 = __floats2half2_rn(cp[2], cp[3]);
            __half2 p2 = __floats2half2_rn(cp[4], cp[5]);
            __half2 p3 = __floats2half2_rn(cp[6], cp[7]);
            *(uint4*)&Y[row * COLS + ncol0 + f * 16 + ch] =
                make_uint4(h2u(p0), h2u(p1), h2u(p2), h2u(p3));
        }
        __syncwarp();
    }
}

// ======================= CSR build (by destination) =========================
__global__ void k_hist(const int* __restrict__ dst) {
    int i = blockIdx.x * blockDim.x + threadIdx.x;
    if (i < EE) g_rank[i] = atomicAdd(&g_cnt[dst[i]], 1);
}

__global__ __launch_bounds__(SCAN_B) void k_scan1() {
    __shared__ int sh[SCAN_B];
    int i = blockIdx.x * SCAN_B + threadIdx.x;
    int v = (i < NN) ? g_cnt[i] : 0;
    if (i < NN) g_cnt[i] = 0;          // restore invariant for next launch
    sh[threadIdx.x] = v;
    __syncthreads();
#pragma unroll
    for (int d = 1; d < SCAN_B; d <<= 1) {
        int t = (threadIdx.x >= d) ? sh[threadIdx.x - d] : 0;
        __syncthreads();
        sh[threadIdx.x] += t;
        __syncthreads();
    }
    if (i < NN) g_off[i] = sh[threadIdx.x] - v;
    if (threadIdx.x == SCAN_B - 1) g_part[blockIdx.x] = sh[SCAN_B - 1];
}

__global__ __launch_bounds__(128) void k_scan2() {
    __shared__ int sh[128];
    int t = threadIdx.x;
    int v = (t < NPART) ? g_part[t] : 0;
    sh[t] = v;
    __syncthreads();
#pragma unroll
    for (int d = 1; d < 128; d <<= 1) {
        int u = (t >= d) ? sh[t - d] : 0;
        __syncthreads();
        sh[t] += u;
        __syncthreads();
    }
    if (t < NPART) g_part[t] = sh[t] - v;
}

__global__ __launch_bounds__(SCAN_B) void k_scan3() {
    int i = blockIdx.x * SCAN_B + threadIdx.x;
    if (i < NN) g_off[i] += g_part[blockIdx.x];
    if (i == 0) g_off[NN] = EE;
}

__global__ void k_scatter(const int* __restrict__ src, const int* __restrict__ dst) {
    int i = blockIdx.x * blockDim.x + threadIdx.x;
    if (i >= EE) return;
    g_csrc[g_off[dst[i]] + g_rank[i]] = src[i];
}

// =================== fused per-node softmax + aggregation ===================
// One warp per node; warp split into 2x16 lanes -> 2 edges per iteration,
// each lane loading 16B (C=128) / 8B (C=64) of its edge's row.
// FUSE (layer1): relu + fp16 output + layer-2 att scalars. !FUSE: fp32 out.
template <int C, bool FUSE>
__global__ __launch_bounds__(256) void k_agg(const __half* __restrict__ H,
                                             const float* __restrict__ bias,
                                             const float* __restrict__ aS,
                                             const float* __restrict__ aD,
                                             float* __restrict__ OutF,
                                             __half* __restrict__ OutH,
                                             const float* __restrict__ wa2) {
    __shared__ int2 stage[8][32];
    int warp = threadIdx.x >> 5;
    int lane = threadIdx.x & 31;
    int grp  = lane >> 4;        // edge-group: 0 handles even, 1 odd
    int sub  = lane & 15;        // column-slice index within the row
    int n = blockIdx.x * 8 + warp;
    if (n >= NN) return;

    int beg = g_off[n];
    int end = g_off[n + 1];
    float ad = aD[n];

    unsigned long long a01 = 0ull, a23 = 0ull, a45 = 0ull, a67 = 0ull;
    float denom = 0.f;

    for (int j0 = beg; j0 < end; j0 += 32) {
        int j = j0 + lane;
        int s = 0;
        float w = 0.f;
        if (j < end) {
            s = g_csrc[j];
            float e = aS[s] + ad;
            e = e > 0.f ? e : 0.2f * e;
            w = __expf(e);
        }
        denom += w;
        stage[warp][lane] = make_int2(s, __float_as_int(w));
        __syncwarp();

        int cnt = min(32, end - j0);
        int npair = (cnt + 1) >> 1;
        // stage entries beyond cnt hold (s=0, w=0): padded pair is a no-op FMA
        if (npair == 16) {
#pragma unroll
            for (int k = 0; k < 16; k++) {
                int2 sw = stage[warp][2 * k + grp];
                float wk = __int_as_float(sw.y);
                unsigned long long w2 = pack2(wk, wk);
                if (C == 128) {
                    uint4 raw = *(const uint4*)&H[sw.x * 128 + sub * 8];
                    float2 f0 = __half22float2(*(const __half2*)&raw.x);
                    float2 f1 = __half22float2(*(const __half2*)&raw.y);
                    float2 f2 = __half22float2(*(const __half2*)&raw.z);
                    float2 f3 = __half22float2(*(const __half2*)&raw.w);
                    fma2(a01, pack2(f0.x, f0.y), w2);
                    fma2(a23, pack2(f1.x, f1.y), w2);
                    fma2(a45, pack2(f2.x, f2.y), w2);
                    fma2(a67, pack2(f3.x, f3.y), w2);
                } else {
                    uint2 raw = *(const uint2*)&H[sw.x * 64 + sub * 4];
                    float2 f0 = __half22float2(*(const __half2*)&raw.x);
                    float2 f1 = __half22float2(*(const __half2*)&raw.y);
                    fma2(a01, pack2(f0.x, f0.y), w2);
                    fma2(a23, pack2(f1.x, f1.y), w2);
                }
            }
        } else {
#pragma unroll 8
            for (int k = 0; k < npair; k++) {
                int2 sw = stage[warp][2 * k + grp];
                float wk = __int_as_float(sw.y);
                unsigned long long w2 = pack2(wk, wk);
                if (C == 128) {
                    uint4 raw = *(const uint4*)&H[sw.x * 128 + sub * 8];
                    float2 f0 = __half22float2(*(const __half2*)&raw.x);
                    float2 f1 = __half22float2(*(const __half2*)&raw.y);
                    float2 f2 = __half22float2(*(const __half2*)&raw.z);
                    float2 f3 = __half22float2(*(const __half2*)&raw.w);
                    fma2(a01, pack2(f0.x, f0.y), w2);
                    fma2(a23, pack2(f1.x, f1.y), w2);
                    fma2(a45, pack2(f2.x, f2.y), w2);
                    fma2(a67, pack2(f3.x, f3.y), w2);
                } else {
                    uint2 raw = *(const uint2*)&H[sw.x * 64 + sub * 4];
                    float2 f0 = __half22float2(*(const __half2*)&raw.x);
                    float2 f1 = __half22float2(*(const __half2*)&raw.y);
                    fma2(a01, pack2(f0.x, f0.y), w2);
                    fma2(a23, pack2(f1.x, f1.y), w2);
                }
            }
        }
        __syncwarp();
    }

    // combine the two edge groups (lane L <-> L^16 hold same column slice)
    add2(a01, __shfl_xor_sync(0xffffffffu, a01, 16));
    add2(a23, __shfl_xor_sync(0xffffffffu, a23, 16));
    if (C == 128) {
        add2(a45, __shfl_xor_sync(0xffffffffu, a45, 16));
        add2(a67, __shfl_xor_sync(0xffffffffu, a67, 16));
    }
#pragma unroll
    for (int o = 16; o > 0; o >>= 1)
        denom += __shfl_xor_sync(0xffffffffu, denom, o);
    float inv = (end > beg) ? __frcp_rn(denom) : 0.f;

    if (C == 128) {
        float v[8];
        unpack2(a01, v[0], v[1]);
        unpack2(a23, v[2], v[3]);
        unpack2(a45, v[4], v[5]);
        unpack2(a67, v[6], v[7]);
        float4 b0 = *(const float4*)&bias[sub * 8];
        float4 b1 = *(const float4*)&bias[sub * 8 + 4];
        v[0] = v[0] * inv + b0.x; v[1] = v[1] * inv + b0.y;
        v[2] = v[2] * inv + b0.z; v[3] = v[3] * inv + b0.w;
        v[4] = v[4] * inv + b1.x; v[5] = v[5] * inv + b1.y;
        v[6] = v[6] * inv + b1.z; v[7] = v[7] * inv + b1.w;
        if (FUSE) {
#pragma unroll
            for (int i = 0; i < 8; i++) v[i] = fmaxf(v[i], 0.f);
            if (lane < 16) {
                __half2 p0 = __floats2half2_rn(v[0], v[1]);
                __half2 p1 = __floats2half2_rn(v[2], v[3]);
                __half2 p2 = __floats2half2_rn(v[4], v[5]);
                __half2 p3 = __floats2half2_rn(v[6], v[7]);
                *(uint4*)&OutH[n * 128 + sub * 8] =
                    make_uint4(h2u(p0), h2u(p1), h2u(p2), h2u(p3));
            }
            // layer-2 attention scalars (only group-0 lanes contribute)
            float s1 = 0.f, s2 = 0.f;
            if (lane < 16) {
                float4 ws0 = *(const float4*)&wa2[sub * 8];
                float4 ws1 = *(const float4*)&wa2[sub * 8 + 4];
                float4 wd0 = *(const float4*)&wa2[128 + sub * 8];
                float4 wd1 = *(const float4*)&wa2[128 + sub * 8 + 4];
                s1 = v[0]*ws0.x + v[1]*ws0.y + v[2]*ws0.z + v[3]*ws0.w
                   + v[4]*ws1.x + v[5]*ws1.y + v[6]*ws1.z + v[7]*ws1.w;
                s2 = v[0]*wd0.x + v[1]*wd0.y + v[2]*wd0.z + v[3]*wd0.w
                   + v[4]*wd1.x + v[5]*wd1.y + v[6]*wd1.z + v[7]*wd1.w;
            }
#pragma unroll
            for (int o = 16; o > 0; o >>= 1) {
                s1 += __shfl_xor_sync(0xffffffffu, s1, o);
                s2 += __shfl_xor_sync(0xffffffffu, s2, o);
            }
            if (lane == 0) { g_asrc2[n] = s1; g_adst2[n] = s2; }
        } else {
            if (lane < 16) {
                *(float4*)&OutF[n * 128 + sub * 8] =
                    make_float4(v[0], v[1], v[2], v[3]);
                *(float4*)&OutF[n * 128 + sub * 8 + 4] =
                    make_float4(v[4], v[5], v[6], v[7]);
            }
        }
    } else {
        float v[4];
        unpack2(a01, v[0], v[1]);
        unpack2(a23, v[2], v[3]);
        if (lane < 16) {
            float4 b = *(const float4*)&bias[sub * 4];
            v[0] = v[0] * inv + b.x; v[1] = v[1] * inv + b.y;
            v[2] = v[2] * inv + b.z; v[3] = v[3] * inv + b.w;
            *(float4*)&OutF[n * 64 + sub * 4] = make_float4(v[0], v[1], v[2], v[3]);
        }
    }
}

// ---------------- launch ----------------------------------------------------
static cudaStream_t g_s2 = nullptr;
static cudaEvent_t  g_evF = nullptr, g_evJ = nullptr;

extern "C" void kernel_launch(void* const* d_in, const int* in_sizes, int n_in,
                              void* d_out, int out_size) {
    const float* x    = (const float*)d_in[0];
    const int*   ei   = (const int*)d_in[1];
    const float* Ws1  = (const float*)d_in[2];
    const float* Wd1  = (const float*)d_in[3];
    const float* as1  = (const float*)d_in[4];
    const float* ad1  = (const float*)d_in[5];
    const float* b1   = (const float*)d_in[6];
    const float* Ws2  = (const float*)d_in[7];
    const float* Wd2  = (const float*)d_in[8];
    const float* as2  = (const float*)d_in[9];
    const float* ad2  = (const float*)d_in[10];
    const float* b2   = (const float*)d_in[11];
    float* out = (float*)d_out;

    const int* src = ei;
    const int* dst = ei + EE;

    __half *p_xh, *p_h1, *p_a1h, *p_h2, *p_W1h, *p_W2h;
    float  *p_wa1, *p_wa2, *p_as, *p_ad, *p_as2, *p_ad2;
    cudaGetSymbolAddress((void**)&p_xh, g_xh);
    cudaGetSymbolAddress((void**)&p_h1, g_h1);
    cudaGetSymbolAddress((void**)&p_a1h, g_a1h);
    cudaGetSymbolAddress((void**)&p_h2, g_h2);
    cudaGetSymbolAddress((void**)&p_W1h, g_W1h);
    cudaGetSymbolAddress((void**)&p_W2h, g_W2h);
    cudaGetSymbolAddress((void**)&p_wa1, g_wa1);
    cudaGetSymbolAddress((void**)&p_wa2, g_wa2);
    cudaGetSymbolAddress((void**)&p_as, g_asrc);
    cudaGetSymbolAddress((void**)&p_ad, g_adst);
    cudaGetSymbolAddress((void**)&p_as2, g_asrc2);
    cudaGetSymbolAddress((void**)&p_ad2, g_adst2);

    constexpr int SM1 = 64 * 136 * 2 + 128 * (HID + 8) * 2 + 8 * 256 * 4;   // 60416
    constexpr int SM2 = 64 * 136 * 2 + 128 * (OUTC + 8) * 2 + 8 * 256 * 4;  // 44032

    if (!g_s2) {
        cudaStreamCreateWithFlags(&g_s2, cudaStreamNonBlocking);
        cudaEventCreateWithFlags(&g_evF, cudaEventDisableTiming);
        cudaEventCreateWithFlags(&g_evJ, cudaEventDisableTiming);
        cudaFuncSetAttribute(k_gemm_wmma<HID>,
                             cudaFuncAttributeMaxDynamicSharedMemorySize, SM1);
        cudaFuncSetAttribute(k_gemm_wmma<OUTC>,
                             cudaFuncAttributeMaxDynamicSharedMemorySize, SM2);
    }

    const int TB = 256;
    const int edge_blocks = (EE + TB - 1) / TB;
    const int agg_blocks  = (NN + 7) / 8;
    const int gemm_blocks = (NN + 63) / 64;   // 1563

    cudaEventRecord(g_evF, 0);
    cudaStreamWaitEvent(g_s2, g_evF, 0);

    // ---------- main: layer-1 dense path ----------
    k_wa<<<1, 128>>>(Ws1, as1, Wd1, ad1, HID, p_wa1);                  // 1
    k_cvtW<<<48, 256>>>(Ws1, Ws2);                                     // 2
    k_cvtX<<<agg_blocks, 256>>>(x, p_wa1);                             // 3
    k_gemm_wmma<HID><<<gemm_blocks, 256, SM1>>>(p_xh, p_W1h, p_h1);    // 4 (profiled)

    // ---------- side stream: CSR build (overlaps dense path) ----------
    k_hist<<<edge_blocks, TB, 0, g_s2>>>(dst);
    k_scan1<<<NPART, SCAN_B, 0, g_s2>>>();
    k_scan2<<<1, 128, 0, g_s2>>>();
    k_scan3<<<NPART, SCAN_B, 0, g_s2>>>();
    k_scatter<<<edge_blocks, TB, 0, g_s2>>>(src, dst);
    cudaEventRecord(g_evJ, g_s2);

    k_wa<<<1, 128>>>(Ws2, as2, Wd2, ad2, OUTC, p_wa2);

    // ---------- layer 1 aggregation (join; fused: fp16 out + att2) ----------
    cudaStreamWaitEvent(0, g_evJ, 0);
    k_agg<HID, true><<<agg_blocks, TB>>>(p_h1, b1, p_as, p_ad,
                                         nullptr, p_a1h, p_wa2);

    // ---------- layer 2 ----------
    k_gemm_wmma<OUTC><<<gemm_blocks, 256, SM2>>>(p_a1h, p_W2h, p_h2);
    k_agg<OUTC, false><<<agg_blocks, TB>>>(p_h2, b2, p_as2, p_ad2,
                                           out, nullptr, nullptr);
}